// round 16
// baseline (speedup 1.0000x reference)
#include <cuda_runtime.h>
#include <cuda_fp16.h>
#include <math.h>

#define Nn 50000
#define Ee 800000
#define Cc 8
#define Mm 32
#define Gg 16

// ---------------- scratch (device globals; no allocation) ----------------
__device__ __align__(16) float g_B0[Cc][Mm][Gg];
__device__ __align__(16) float g_Pi[Cc][Gg];
__device__ __align__(16) float g_Q[3][Cc][Cc][Gg];
__device__ __align__(16) float g_B[3][Cc][Mm][Gg];

__device__ int   g_cnt[Nn];
__device__ float g_inv[Nn];
__device__ int   g_ptr[Nn];
__device__ int   g_cur[Nn];
__device__ int   g_total;
__device__ __align__(16) int g_srt[Ee];
// h stored as fp16: per node flat c-major row of 128 halves = 256 B
__device__ __align__(16) uint2 g_hA[Nn * 32];
__device__ __align__(16) uint2 g_hB[Nn * 32];

// ---------------- small helpers ----------------
__device__ __forceinline__ float4 f4mul(float4 a, float4 b) {
    return make_float4(a.x * b.x, a.y * b.y, a.z * b.z, a.w * b.w);
}
__device__ __forceinline__ void accum4(uint4 v, float* a) {
    float2 p0 = __half22float2(*reinterpret_cast<half2*>(&v.x));
    float2 p1 = __half22float2(*reinterpret_cast<half2*>(&v.y));
    float2 p2 = __half22float2(*reinterpret_cast<half2*>(&v.z));
    float2 p3 = __half22float2(*reinterpret_cast<half2*>(&v.w));
    a[0] += p0.x; a[1] += p0.y; a[2] += p1.x; a[3] += p1.y;
    a[4] += p2.x; a[5] += p2.y; a[6] += p3.x; a[7] += p3.y;
}
__device__ __forceinline__ uint2 pack_h(float4 u) {
    half2 lo = __floats2half2_rn(u.x, u.y);
    half2 hi = __floats2half2_rn(u.z, u.w);
    uint2 r;
    r.x = *reinterpret_cast<unsigned int*>(&lo);
    r.y = *reinterpret_cast<unsigned int*>(&hi);
    return r;
}

// ---------------- prep: softmaxes (block 0) + zero counters (blocks 1..) ----------------
__global__ void k_prep(const float* __restrict__ lB0, const float* __restrict__ lPi,
                       const float* __restrict__ lQ, const float* __restrict__ lB) {
    int t = threadIdx.x;
    if (blockIdx.x > 0) {
        int i = (blockIdx.x - 1) * 512 + t;
        if (i < Nn) g_cnt[i] = 0;
        if (blockIdx.x == 1 && t == 0) g_total = 0;
        return;
    }
    if (t < 128) {
        int c = t >> 4, g = t & 15;
        float mx = -1e30f;
        for (int m = 0; m < Mm; m++) mx = fmaxf(mx, lB0[(c * Mm + m) * Gg + g]);
        float s = 0.f, e[Mm];
        for (int m = 0; m < Mm; m++) { float v = __expf(lB0[(c * Mm + m) * Gg + g] - mx); e[m] = v; s += v; }
        float inv = 1.f / s;
        for (int m = 0; m < Mm; m++) g_B0[c][m][g] = e[m] * inv;
    }
    if (t >= 128 && t < 144) {
        int g = t - 128;
        float mx = -1e30f;
        for (int c = 0; c < Cc; c++) mx = fmaxf(mx, lPi[c * Gg + g]);
        float s = 0.f, e[Cc];
        for (int c = 0; c < Cc; c++) { float v = __expf(lPi[c * Gg + g] - mx); e[c] = v; s += v; }
        float inv = 1.f / s;
        for (int c = 0; c < Cc; c++) g_Pi[c][g] = e[c] * inv;
    }
    if (t < 384) {
        int l = t / 128, r = t % 128, k = r >> 4, g = r & 15;
        const float* base = lQ + l * Cc * Cc * Gg;
        float mx = -1e30f;
        for (int i = 0; i < Cc; i++) mx = fmaxf(mx, base[(i * Cc + k) * Gg + g]);
        float s = 0.f, e[Cc];
        for (int i = 0; i < Cc; i++) { float v = __expf(base[(i * Cc + k) * Gg + g] - mx); e[i] = v; s += v; }
        float inv = 1.f / s;
        for (int i = 0; i < Cc; i++) g_Q[l][i][k][g] = e[i] * inv;
    }
    if (t < 384) {
        int l = t / 128, r = t % 128, c = r >> 4, g = r & 15;
        const float* base = lB + l * Cc * Mm * Gg;
        float mx = -1e30f;
        for (int m = 0; m < Mm; m++) mx = fmaxf(mx, base[(c * Mm + m) * Gg + g]);
        float s = 0.f, e[Mm];
        for (int m = 0; m < Mm; m++) { float v = __expf(base[(c * Mm + m) * Gg + g] - mx); e[m] = v; s += v; }
        float inv = 1.f / s;
        for (int m = 0; m < Mm; m++) g_B[l][c][m][g] = e[m] * inv;
    }
}

// ---------------- CSR build (1 edge per thread: measured optimum) ----------------
__global__ void k_deg(const int* __restrict__ ei) {
    int e = blockIdx.x * blockDim.x + threadIdx.x;
    if (e < Ee) atomicAdd(&g_cnt[ei[e]], 1);
}

// block-local inclusive scan + one atomic per block for the base offset
__global__ void k_ptr2() {
    __shared__ int sh[256];
    __shared__ int base;
    int i = blockIdx.x * 256 + threadIdx.x;
    int v = (i < Nn) ? g_cnt[i] : 0;
    sh[threadIdx.x] = v;
    __syncthreads();
    for (int s = 1; s < 256; s <<= 1) {
        int a = (threadIdx.x >= s) ? sh[threadIdx.x - s] : 0;
        __syncthreads();
        sh[threadIdx.x] += a;
        __syncthreads();
    }
    if (threadIdx.x == 255) base = atomicAdd(&g_total, sh[255]);
    __syncthreads();
    if (i < Nn) {
        int excl = sh[threadIdx.x] - v + base;
        g_ptr[i] = excl;
        g_cur[i] = excl;
        g_inv[i] = 1.f / fmaxf((float)v, 1.f);
    }
}

__global__ void k_scatter(const int* __restrict__ ei) {
    int e = blockIdx.x * blockDim.x + threadIdx.x;
    if (e < Ee) {
        int d = ei[e];                       // dst row
        int p = atomicAdd(&g_cur[d], 1);
        g_srt[p] = ei[Ee + e];               // src row
    }
}

// ---------------- layer 0 ----------------
__global__ void k_layer0(const int* __restrict__ x, float* __restrict__ out) {
    int w = (blockIdx.x * blockDim.x + threadIdx.x) >> 5;
    int lane = threadIdx.x & 31;
    if (w >= Nn) return;
    int c = lane >> 2, gq = lane & 3;
    int xn = x[w];
    float4 b0 = *(const float4*)&g_B0[c][xn][gq * 4];
    float4 pi = *(const float4*)&g_Pi[c][gq * 4];
    float4 u = f4mul(b0, pi);
    float4 Z = u;
    #pragma unroll
    for (int m = 4; m < 32; m <<= 1) {
        Z.x += __shfl_xor_sync(0xffffffffu, Z.x, m);
        Z.y += __shfl_xor_sync(0xffffffffu, Z.y, m);
        Z.z += __shfl_xor_sync(0xffffffffu, Z.z, m);
        Z.w += __shfl_xor_sync(0xffffffffu, Z.w, m);
    }
    g_hA[w * 32 + lane] = pack_h(make_float4(u.x / Z.x, u.y / Z.y, u.z / Z.z, u.w / Z.w));
    if (c == 0) {
        *(float4*)&out[w * 64 + gq * 4] =
            make_float4(__logf(Z.x), __logf(Z.y), __logf(Z.z), __logf(Z.w));
    }
}

// ---------------- fused graph layer (exact R8-proven 146.1us structure) ----------------
// Lanes 0-15 serve even edges of each pair, 16-31 odd; each lane loads one
// uint4 (16B) chunk of the 256B h-row; 8-edge unroll = 4 LDG.128 in flight.
// Launched at 192 threads/block: regs=48 -> 7 blocks/SM = 42 warps (vs 40 at
// 256) with identical codegen (launch_bounds cap unchanged).
__global__ void __launch_bounds__(256) k_layer(const int* __restrict__ x, float* __restrict__ out,
                                               int l, int flip) {
    int w = (blockIdx.x * blockDim.x + threadIdx.x) >> 5;
    int lane = threadIdx.x & 31;
    if (w >= Nn) return;
    int c = lane >> 2, gq = lane & 3;
    int half = lane >> 4;     // which edge of the pair this lane serves
    int j = lane & 15;        // uint4 chunk index within the 256B row

    const uint2* __restrict__ hin = flip ? g_hB : g_hA;
    uint2* __restrict__ hout      = flip ? g_hA : g_hB;
    const uint4* __restrict__ hin4 = reinterpret_cast<const uint4*>(hin);

    int start = g_ptr[w];
    int deg = g_cnt[w];
    float inv = g_inv[w];

    float a[8];
    #pragma unroll
    for (int k = 0; k < 8; k++) a[k] = 0.f;

    int e = start, end = start + deg;
    for (; e + 8 <= end; e += 8) {
        int s0 = g_srt[e + 0 + half];
        int s1 = g_srt[e + 2 + half];
        int s2 = g_srt[e + 4 + half];
        int s3 = g_srt[e + 6 + half];
        uint4 v0 = hin4[s0 * 16 + j];
        uint4 v1 = hin4[s1 * 16 + j];
        uint4 v2 = hin4[s2 * 16 + j];
        uint4 v3 = hin4[s3 * 16 + j];
        accum4(v0, a); accum4(v1, a); accum4(v2, a); accum4(v3, a);
    }
    for (; e + 2 <= end; e += 2) {
        int s = g_srt[e + half];
        accum4(hin4[s * 16 + j], a);
    }
    if (e < end && half == 0) {
        accum4(hin4[g_srt[e] * 16 + j], a);
    }
    // fold the two edge-halves
    #pragma unroll
    for (int k = 0; k < 8; k++) a[k] += __shfl_xor_sync(0xffffffffu, a[k], 16);

    // redistribute chunk layout -> (c,gq) float4 layout
    int srcl = (c << 1) + (gq >> 1);
    float4 aggr;
    {
        float lo0 = __shfl_sync(0xffffffffu, a[0], srcl);
        float lo1 = __shfl_sync(0xffffffffu, a[1], srcl);
        float lo2 = __shfl_sync(0xffffffffu, a[2], srcl);
        float lo3 = __shfl_sync(0xffffffffu, a[3], srcl);
        float hi0 = __shfl_sync(0xffffffffu, a[4], srcl);
        float hi1 = __shfl_sync(0xffffffffu, a[5], srcl);
        float hi2 = __shfl_sync(0xffffffffu, a[6], srcl);
        float hi3 = __shfl_sync(0xffffffffu, a[7], srcl);
        bool upper = (gq & 1);
        aggr.x = upper ? hi0 : lo0;
        aggr.y = upper ? hi1 : lo1;
        aggr.z = upper ? hi2 : lo2;
        aggr.w = upper ? hi3 : lo3;
    }
    aggr.x *= inv; aggr.y *= inv; aggr.z *= inv; aggr.w *= inv;

    // QA[c,g] = sum_k Q[c,k,g] * aggr[k,g]
    float4 QA = make_float4(0.f, 0.f, 0.f, 0.f);
    #pragma unroll
    for (int k = 0; k < Cc; k++) {
        int sl = k * 4 + gq;
        float4 t;
        t.x = __shfl_sync(0xffffffffu, aggr.x, sl);
        t.y = __shfl_sync(0xffffffffu, aggr.y, sl);
        t.z = __shfl_sync(0xffffffffu, aggr.z, sl);
        t.w = __shfl_sync(0xffffffffu, aggr.w, sl);
        float4 q = *(const float4*)&g_Q[l][c][k][gq * 4];
        QA.x += q.x * t.x; QA.y += q.y * t.y; QA.z += q.z * t.z; QA.w += q.w * t.w;
    }

    int xn = x[w];
    float4 b = *(const float4*)&g_B[l][c][xn][gq * 4];
    float4 u = f4mul(b, QA);

    float4 Z = u;
    #pragma unroll
    for (int m = 4; m < 32; m <<= 1) {
        Z.x += __shfl_xor_sync(0xffffffffu, Z.x, m);
        Z.y += __shfl_xor_sync(0xffffffffu, Z.y, m);
        Z.z += __shfl_xor_sync(0xffffffffu, Z.z, m);
        Z.w += __shfl_xor_sync(0xffffffffu, Z.w, m);
    }

    hout[w * 32 + lane] = pack_h(make_float4(u.x / Z.x, u.y / Z.y, u.z / Z.z, u.w / Z.w));
    if (c == 0) {
        *(float4*)&out[w * 64 + (l + 1) * 16 + gq * 4] =
            make_float4(__logf(Z.x), __logf(Z.y), __logf(Z.z), __logf(Z.w));
    }
}

// ---------------- launch ----------------
extern "C" void kernel_launch(void* const* d_in, const int* in_sizes, int n_in,
                              void* d_out, int out_size) {
    const int*   x   = (const int*)d_in[0];
    const int*   ei  = (const int*)d_in[1];   // [2,E]: row0=dst, row1=src
    const float* lB0 = (const float*)d_in[2];
    const float* lPi = (const float*)d_in[3];
    const float* lQ  = (const float*)d_in[4];
    const float* lB  = (const float*)d_in[5];
    float* out = (float*)d_out;

    k_prep<<<1 + (Nn + 511) / 512, 512>>>(lB0, lPi, lQ, lB);
    k_deg<<<(Ee + 255) / 256, 256>>>(ei);
    k_ptr2<<<(Nn + 255) / 256, 256>>>();
    k_scatter<<<(Ee + 255) / 256, 256>>>(ei);

    int nwblocks256 = (Nn * 32 + 255) / 256;
    int nwblocks192 = (Nn * 32 + 191) / 192;
    k_layer0<<<nwblocks256, 256>>>(x, out);
    k_layer<<<nwblocks192, 192>>>(x, out, 0, 0);  // A -> B
    k_layer<<<nwblocks192, 192>>>(x, out, 1, 1);  // B -> A
    k_layer<<<nwblocks192, 192>>>(x, out, 2, 0);  // A -> B
}

// round 17
// speedup vs baseline: 1.5536x; 1.5536x over previous
#include <cuda_runtime.h>
#include <cuda_fp16.h>
#include <math.h>

#define Nn 50000
#define Ee 800000
#define Cc 8
#define Mm 32
#define Gg 16

// ---------------- scratch (device globals; no allocation) ----------------
__device__ __align__(16) float g_B0[Cc][Mm][Gg];
__device__ __align__(16) float g_Pi[Cc][Gg];
__device__ __align__(16) float g_Q[3][Cc][Cc][Gg];
__device__ __align__(16) float g_B[3][Cc][Mm][Gg];

__device__ int   g_cnt[Nn];
__device__ float g_inv[Nn];
__device__ int   g_ptr[Nn];
__device__ int   g_cur[Nn];
__device__ int   g_total;
__device__ int   g_srt[Ee];
// h stored as fp16: per node flat c-major row of 128 halves = 256 B
__device__ __align__(16) uint2 g_hA[Nn * 32];
__device__ __align__(16) uint2 g_hB[Nn * 32];

// ---------------- small helpers ----------------
__device__ __forceinline__ float4 f4mul(float4 a, float4 b) {
    return make_float4(a.x * b.x, a.y * b.y, a.z * b.z, a.w * b.w);
}
__device__ __forceinline__ void accum4(uint4 v, float* a) {
    float2 p0 = __half22float2(*reinterpret_cast<half2*>(&v.x));
    float2 p1 = __half22float2(*reinterpret_cast<half2*>(&v.y));
    float2 p2 = __half22float2(*reinterpret_cast<half2*>(&v.z));
    float2 p3 = __half22float2(*reinterpret_cast<half2*>(&v.w));
    a[0] += p0.x; a[1] += p0.y; a[2] += p1.x; a[3] += p1.y;
    a[4] += p2.x; a[5] += p2.y; a[6] += p3.x; a[7] += p3.y;
}
__device__ __forceinline__ uint2 pack_h(float4 u) {
    half2 lo = __floats2half2_rn(u.x, u.y);
    half2 hi = __floats2half2_rn(u.z, u.w);
    uint2 r;
    r.x = *reinterpret_cast<unsigned int*>(&lo);
    r.y = *reinterpret_cast<unsigned int*>(&hi);
    return r;
}

// ---------------- prep: softmaxes (block 0) + zero counters (blocks 1..) ----------------
__global__ void k_prep(const float* __restrict__ lB0, const float* __restrict__ lPi,
                       const float* __restrict__ lQ, const float* __restrict__ lB) {
    int t = threadIdx.x;
    if (blockIdx.x > 0) {
        int i = (blockIdx.x - 1) * 512 + t;
        if (i < Nn) g_cnt[i] = 0;
        if (blockIdx.x == 1 && t == 0) g_total = 0;
        return;
    }
    if (t < 128) {
        int c = t >> 4, g = t & 15;
        float mx = -1e30f;
        for (int m = 0; m < Mm; m++) mx = fmaxf(mx, lB0[(c * Mm + m) * Gg + g]);
        float s = 0.f, e[Mm];
        for (int m = 0; m < Mm; m++) { float v = __expf(lB0[(c * Mm + m) * Gg + g] - mx); e[m] = v; s += v; }
        float inv = 1.f / s;
        for (int m = 0; m < Mm; m++) g_B0[c][m][g] = e[m] * inv;
    }
    if (t >= 128 && t < 144) {
        int g = t - 128;
        float mx = -1e30f;
        for (int c = 0; c < Cc; c++) mx = fmaxf(mx, lPi[c * Gg + g]);
        float s = 0.f, e[Cc];
        for (int c = 0; c < Cc; c++) { float v = __expf(lPi[c * Gg + g] - mx); e[c] = v; s += v; }
        float inv = 1.f / s;
        for (int c = 0; c < Cc; c++) g_Pi[c][g] = e[c] * inv;
    }
    if (t < 384) {
        int l = t / 128, r = t % 128, k = r >> 4, g = r & 15;
        const float* base = lQ + l * Cc * Cc * Gg;
        float mx = -1e30f;
        for (int i = 0; i < Cc; i++) mx = fmaxf(mx, base[(i * Cc + k) * Gg + g]);
        float s = 0.f, e[Cc];
        for (int i = 0; i < Cc; i++) { float v = __expf(base[(i * Cc + k) * Gg + g] - mx); e[i] = v; s += v; }
        float inv = 1.f / s;
        for (int i = 0; i < Cc; i++) g_Q[l][i][k][g] = e[i] * inv;
    }
    if (t < 384) {
        int l = t / 128, r = t % 128, c = r >> 4, g = r & 15;
        const float* base = lB + l * Cc * Mm * Gg;
        float mx = -1e30f;
        for (int m = 0; m < Mm; m++) mx = fmaxf(mx, base[(c * Mm + m) * Gg + g]);
        float s = 0.f, e[Mm];
        for (int m = 0; m < Mm; m++) { float v = __expf(base[(c * Mm + m) * Gg + g] - mx); e[m] = v; s += v; }
        float inv = 1.f / s;
        for (int m = 0; m < Mm; m++) g_B[l][c][m][g] = e[m] * inv;
    }
}

// ---------------- CSR build (1 edge per thread: measured optimum) ----------------
__global__ void k_deg(const int* __restrict__ ei) {
    int e = blockIdx.x * blockDim.x + threadIdx.x;
    if (e < Ee) atomicAdd(&g_cnt[ei[e]], 1);
}

// block-local inclusive scan + one atomic per block for the base offset
__global__ void k_ptr2() {
    __shared__ int sh[256];
    __shared__ int base;
    int i = blockIdx.x * 256 + threadIdx.x;
    int v = (i < Nn) ? g_cnt[i] : 0;
    sh[threadIdx.x] = v;
    __syncthreads();
    for (int s = 1; s < 256; s <<= 1) {
        int a = (threadIdx.x >= s) ? sh[threadIdx.x - s] : 0;
        __syncthreads();
        sh[threadIdx.x] += a;
        __syncthreads();
    }
    if (threadIdx.x == 255) base = atomicAdd(&g_total, sh[255]);
    __syncthreads();
    if (i < Nn) {
        int excl = sh[threadIdx.x] - v + base;
        g_ptr[i] = excl;
        g_cur[i] = excl;
        g_inv[i] = 1.f / fmaxf((float)v, 1.f);
    }
}

__global__ void k_scatter(const int* __restrict__ ei) {
    int e = blockIdx.x * blockDim.x + threadIdx.x;
    if (e < Ee) {
        int d = ei[e];                       // dst row
        int p = atomicAdd(&g_cur[d], 1);
        g_srt[p] = ei[Ee + e];               // src row
    }
}

// ---------------- layer 0 ----------------
__global__ void k_layer0(const int* __restrict__ x, float* __restrict__ out) {
    int w = (blockIdx.x * blockDim.x + threadIdx.x) >> 5;
    int lane = threadIdx.x & 31;
    if (w >= Nn) return;
    int c = lane >> 2, gq = lane & 3;
    int xn = x[w];
    float4 b0 = *(const float4*)&g_B0[c][xn][gq * 4];
    float4 pi = *(const float4*)&g_Pi[c][gq * 4];
    float4 u = f4mul(b0, pi);
    float4 Z = u;
    #pragma unroll
    for (int m = 4; m < 32; m <<= 1) {
        Z.x += __shfl_xor_sync(0xffffffffu, Z.x, m);
        Z.y += __shfl_xor_sync(0xffffffffu, Z.y, m);
        Z.z += __shfl_xor_sync(0xffffffffu, Z.z, m);
        Z.w += __shfl_xor_sync(0xffffffffu, Z.w, m);
    }
    g_hA[w * 32 + lane] = pack_h(make_float4(u.x / Z.x, u.y / Z.y, u.z / Z.z, u.w / Z.w));
    if (c == 0) {
        *(float4*)&out[w * 64 + gq * 4] =
            make_float4(__logf(Z.x), __logf(Z.y), __logf(Z.z), __logf(Z.w));
    }
}

// ---------------- fused graph layer (proven 146.1us structure) ----------------
// Lanes 0-15 serve even edges of each pair, 16-31 odd; each lane loads one
// uint4 (16B) chunk of the 256B h-row; 8-edge unroll = 4 LDG.128 in flight.
__global__ void __launch_bounds__(256) k_layer(const int* __restrict__ x, float* __restrict__ out,
                                               int l, int flip) {
    int w = (blockIdx.x * blockDim.x + threadIdx.x) >> 5;
    int lane = threadIdx.x & 31;
    if (w >= Nn) return;
    int c = lane >> 2, gq = lane & 3;
    int half = lane >> 4;     // which edge of the pair this lane serves
    int j = lane & 15;        // uint4 chunk index within the 256B row

    const uint2* __restrict__ hin = flip ? g_hB : g_hA;
    uint2* __restrict__ hout      = flip ? g_hA : g_hB;
    const uint4* __restrict__ hin4 = reinterpret_cast<const uint4*>(hin);

    int start = g_ptr[w];
    int deg = g_cnt[w];
    float inv = g_inv[w];

    float a[8];
    #pragma unroll
    for (int k = 0; k < 8; k++) a[k] = 0.f;

    int e = start, end = start + deg;
    for (; e + 8 <= end; e += 8) {
        int s0 = g_srt[e + 0 + half];
        int s1 = g_srt[e + 2 + half];
        int s2 = g_srt[e + 4 + half];
        int s3 = g_srt[e + 6 + half];
        uint4 v0 = hin4[s0 * 16 + j];
        uint4 v1 = hin4[s1 * 16 + j];
        uint4 v2 = hin4[s2 * 16 + j];
        uint4 v3 = hin4[s3 * 16 + j];
        accum4(v0, a); accum4(v1, a); accum4(v2, a); accum4(v3, a);
    }
    for (; e + 2 <= end; e += 2) {
        int s = g_srt[e + half];
        accum4(hin4[s * 16 + j], a);
    }
    if (e < end && half == 0) {
        accum4(hin4[g_srt[e] * 16 + j], a);
    }
    // fold the two edge-halves
    #pragma unroll
    for (int k = 0; k < 8; k++) a[k] += __shfl_xor_sync(0xffffffffu, a[k], 16);

    // redistribute chunk layout -> (c,gq) float4 layout
    int srcl = (c << 1) + (gq >> 1);
    float4 aggr;
    {
        float lo0 = __shfl_sync(0xffffffffu, a[0], srcl);
        float lo1 = __shfl_sync(0xffffffffu, a[1], srcl);
        float lo2 = __shfl_sync(0xffffffffu, a[2], srcl);
        float lo3 = __shfl_sync(0xffffffffu, a[3], srcl);
        float hi0 = __shfl_sync(0xffffffffu, a[4], srcl);
        float hi1 = __shfl_sync(0xffffffffu, a[5], srcl);
        float hi2 = __shfl_sync(0xffffffffu, a[6], srcl);
        float hi3 = __shfl_sync(0xffffffffu, a[7], srcl);
        bool upper = (gq & 1);
        aggr.x = upper ? hi0 : lo0;
        aggr.y = upper ? hi1 : lo1;
        aggr.z = upper ? hi2 : lo2;
        aggr.w = upper ? hi3 : lo3;
    }
    aggr.x *= inv; aggr.y *= inv; aggr.z *= inv; aggr.w *= inv;

    // QA[c,g] = sum_k Q[c,k,g] * aggr[k,g]
    float4 QA = make_float4(0.f, 0.f, 0.f, 0.f);
    #pragma unroll
    for (int k = 0; k < Cc; k++) {
        int sl = k * 4 + gq;
        float4 t;
        t.x = __shfl_sync(0xffffffffu, aggr.x, sl);
        t.y = __shfl_sync(0xffffffffu, aggr.y, sl);
        t.z = __shfl_sync(0xffffffffu, aggr.z, sl);
        t.w = __shfl_sync(0xffffffffu, aggr.w, sl);
        float4 q = *(const float4*)&g_Q[l][c][k][gq * 4];
        QA.x += q.x * t.x; QA.y += q.y * t.y; QA.z += q.z * t.z; QA.w += q.w * t.w;
    }

    int xn = x[w];
    float4 b = *(const float4*)&g_B[l][c][xn][gq * 4];
    float4 u = f4mul(b, QA);

    float4 Z = u;
    #pragma unroll
    for (int m = 4; m < 32; m <<= 1) {
        Z.x += __shfl_xor_sync(0xffffffffu, Z.x, m);
        Z.y += __shfl_xor_sync(0xffffffffu, Z.y, m);
        Z.z += __shfl_xor_sync(0xffffffffu, Z.z, m);
        Z.w += __shfl_xor_sync(0xffffffffu, Z.w, m);
    }

    hout[w * 32 + lane] = pack_h(make_float4(u.x / Z.x, u.y / Z.y, u.z / Z.z, u.w / Z.w));
    if (c == 0) {
        *(float4*)&out[w * 64 + (l + 1) * 16 + gq * 4] =
            make_float4(__logf(Z.x), __logf(Z.y), __logf(Z.z), __logf(Z.w));
    }
}

// ---------------- launch ----------------
extern "C" void kernel_launch(void* const* d_in, const int* in_sizes, int n_in,
                              void* d_out, int out_size) {
    const int*   x   = (const int*)d_in[0];
    const int*   ei  = (const int*)d_in[1];   // [2,E]: row0=dst, row1=src
    const float* lB0 = (const float*)d_in[2];
    const float* lPi = (const float*)d_in[3];
    const float* lQ  = (const float*)d_in[4];
    const float* lB  = (const float*)d_in[5];
    float* out = (float*)d_out;

    k_prep<<<1 + (Nn + 511) / 512, 512>>>(lB0, lPi, lQ, lB);
    k_deg<<<(Ee + 255) / 256, 256>>>(ei);
    k_ptr2<<<(Nn + 255) / 256, 256>>>();
    k_scatter<<<(Ee + 255) / 256, 256>>>(ei);

    int nwblocks = (Nn * 32 + 255) / 256;
    k_layer0<<<nwblocks, 256>>>(x, out);
    k_layer<<<nwblocks, 256>>>(x, out, 0, 0);  // A -> B
    k_layer<<<nwblocks, 256>>>(x, out, 1, 1);  // B -> A
    k_layer<<<nwblocks, 256>>>(x, out, 2, 0);  // A -> B
}